// round 15
// baseline (speedup 1.0000x reference)
#include <cuda_runtime.h>

#define N_NODES   50000
#define N_EDGES   800000
#define D         96
#define OUT_COLS  384            // 4 * D (concat of x,h1,h2,h3)
#define M_TILE    64             // rows per fused block
#define IN_LD     100            // padded smem row stride (floats)

#define SCAN_BS   512
#define SCAN_NB   ((N_NODES + SCAN_BS - 1) / SCAN_BS)   // 98

// CSR scratch in globals.
__device__ int g_cnt[N_NODES];
__device__ int g_rowptr[N_NODES + 1];
__device__ int g_csr[N_EDGES];
__device__ int g_blksum[SCAN_NB];
__device__ int g_blkoff[SCAN_NB];

typedef unsigned long long ull;
__device__ __forceinline__ ull pack2(float lo, float hi) {
    ull r; asm("mov.b64 %0, {%1, %2};" : "=l"(r) : "f"(lo), "f"(hi)); return r;
}
__device__ __forceinline__ void unpack2(ull v, float& lo, float& hi) {
    asm("mov.b64 {%0, %1}, %2;" : "=f"(lo), "=f"(hi) : "l"(v));
}
__device__ __forceinline__ void fma2(ull& d, ull a, ull b) {
    asm("fma.rn.f32x2 %0, %1, %2, %0;" : "+l"(d) : "l"(a), "l"(b));
}

// --------------------------- CSR build --------------------------------------
__global__ void count_kernel(const int* __restrict__ ei) {
    int e = blockIdx.x * blockDim.x + threadIdx.x;
    if (e < N_EDGES) atomicAdd(&g_cnt[ei[N_EDGES + e]], 1);
}
__global__ void scan_a_kernel() {
    __shared__ int sh[SCAN_BS];
    int t = threadIdx.x;
    int i = blockIdx.x * SCAN_BS + t;
    int v = (i < N_NODES) ? g_cnt[i] : 0;
    sh[t] = v;
    __syncthreads();
    for (int off = 1; off < SCAN_BS; off <<= 1) {
        int u = (t >= off) ? sh[t - off] : 0;
        __syncthreads();
        sh[t] += u;
        __syncthreads();
    }
    if (i < N_NODES) g_rowptr[i] = sh[t] - v;
    if (t == SCAN_BS - 1) g_blksum[blockIdx.x] = sh[t];
}
__global__ void scan_b_kernel() {
    __shared__ int sh[128];
    int t = threadIdx.x;
    int v = (t < SCAN_NB) ? g_blksum[t] : 0;
    sh[t] = v;
    __syncthreads();
    for (int off = 1; off < 128; off <<= 1) {
        int u = (t >= off) ? sh[t - off] : 0;
        __syncthreads();
        sh[t] += u;
        __syncthreads();
    }
    if (t < SCAN_NB) g_blkoff[t] = sh[t] - v;
}
__global__ void scan_c_kernel() {
    int i = blockIdx.x * blockDim.x + threadIdx.x;
    if (i < N_NODES) {
        int r = g_rowptr[i] + g_blkoff[i / SCAN_BS];
        g_rowptr[i] = r;
        g_cnt[i]    = r;
    }
    if (i == 0) g_rowptr[N_NODES] = N_EDGES;
}
__global__ void fill_kernel(const int* __restrict__ ei) {
    int e = blockIdx.x * blockDim.x + threadIdx.x;
    if (e >= N_EDGES) return;
    int src = ei[e];
    int dst = ei[N_EDGES + e];
    int pos = atomicAdd(&g_cnt[dst], 1);
    g_csr[pos] = src;
}

// ---------------------------------------------------------------------------
// fused layer: gather CSR aggregation into smem (8-wide batched loads ->
// ~8 LDG.128 in flight per warp, L2-cap), then relu(in@w1+b1)@w2+b2.
// FFMA2 k-pair scheme; sW[p*96+j] = (w[2p][j], w[2p+1][j]).
// smem = 36864 + 2*25600 = 88064 B -> 2 blocks/SM.
// ---------------------------------------------------------------------------
__global__ __launch_bounds__(256) void fused_layer_kernel(
        const float* __restrict__ cur, int cs,
        const float* __restrict__ w1, const float* __restrict__ b1,
        const float* __restrict__ w2, const float* __restrict__ b2,
        float* __restrict__ self0, float* __restrict__ dst) {
    extern __shared__ char smem[];
    ull*   sW   = reinterpret_cast<ull*>(smem);                  // 4608 ull
    float* sIn  = reinterpret_cast<float*>(smem + 36864);        // 64*100
    float* sTmp = reinterpret_cast<float*>(smem + 36864 + 25600);// 64*100

    const int tid = threadIdx.x;
    const int tx  = tid & 15;             // 6 output cols each
    const int ty  = tid >> 4;             // 4 output rows each
    const int rowBase = blockIdx.x * M_TILE;
    const int cs4 = cs / 4;
    const float4* curv = reinterpret_cast<const float4*>(cur);

    // ---- interleaved w1 load ----
    #pragma unroll
    for (int i = 0; i < 18; ++i) {
        int idx = tid + 256 * i;
        int p = idx / 96, j = idx % 96;
        sW[idx] = pack2(w1[(2 * p) * D + j], w1[(2 * p + 1) * D + j]);
    }

    // ---- gather: sIn[r] = cur[row] + sum_neighbors cur[src] ----
    #pragma unroll
    for (int i = 0; i < 6; ++i) {
        int u = tid + 256 * i;            // 64 rows x 24 float4-chunks
        int r = u / 24, c = u % 24;
        int row = rowBase + r;
        float4 acc = make_float4(0.f, 0.f, 0.f, 0.f);
        if (row < N_NODES) {
            float4 self = __ldg(&curv[(size_t)row * cs4 + c]);
            if (self0)
                *reinterpret_cast<float4*>(self0 + (size_t)row * OUT_COLS + c * 4) = self;
            acc = self;
            int j = g_rowptr[row], end = g_rowptr[row + 1];
            // 8-wide batches: all loads issued before any adds (MLP ~8)
            for (; j + 8 <= end; j += 8) {
                int s[8];
                #pragma unroll
                for (int q = 0; q < 8; ++q) s[q] = g_csr[j + q];
                float4 v[8];
                #pragma unroll
                for (int q = 0; q < 8; ++q)
                    v[q] = __ldg(&curv[(size_t)s[q] * cs4 + c]);
                #pragma unroll
                for (int q = 0; q < 8; ++q) {
                    acc.x += v[q].x; acc.y += v[q].y;
                    acc.z += v[q].z; acc.w += v[q].w;
                }
            }
            if (j + 4 <= end) {
                int s[4];
                #pragma unroll
                for (int q = 0; q < 4; ++q) s[q] = g_csr[j + q];
                float4 v[4];
                #pragma unroll
                for (int q = 0; q < 4; ++q)
                    v[q] = __ldg(&curv[(size_t)s[q] * cs4 + c]);
                #pragma unroll
                for (int q = 0; q < 4; ++q) {
                    acc.x += v[q].x; acc.y += v[q].y;
                    acc.z += v[q].z; acc.w += v[q].w;
                }
                j += 4;
            }
            for (; j < end; ++j) {
                float4 v = __ldg(&curv[(size_t)g_csr[j] * cs4 + c]);
                acc.x += v.x; acc.y += v.y; acc.z += v.z; acc.w += v.w;
            }
        }
        *reinterpret_cast<float4*>(sIn + r * IN_LD + c * 4) = acc;
    }
    __syncthreads();

    ull acc2[4][6];
    // ---- phase 1: tmp = relu(in @ w1 + b1) ----
    #pragma unroll
    for (int r = 0; r < 4; ++r)
        #pragma unroll
        for (int j = 0; j < 6; ++j) acc2[r][j] = pack2(0.f, 0.f);

    #pragma unroll 4
    for (int p = 0; p < D / 2; ++p) {
        ull a2[4];
        #pragma unroll
        for (int r = 0; r < 4; ++r)
            a2[r] = *reinterpret_cast<const ull*>(sIn + (ty * 4 + r) * IN_LD + 2 * p);
        const ull* bp = sW + p * 96 + tx * 6;
        ull b0 = bp[0], b1v = bp[1], b2v = bp[2], b3 = bp[3], b4 = bp[4], b5 = bp[5];
        #pragma unroll
        for (int r = 0; r < 4; ++r) {
            fma2(acc2[r][0], a2[r], b0);
            fma2(acc2[r][1], a2[r], b1v);
            fma2(acc2[r][2], a2[r], b2v);
            fma2(acc2[r][3], a2[r], b3);
            fma2(acc2[r][4], a2[r], b4);
            fma2(acc2[r][5], a2[r], b5);
        }
    }
    #pragma unroll
    for (int r = 0; r < 4; ++r) {
        float* tp = sTmp + (ty * 4 + r) * IN_LD + tx * 6;
        #pragma unroll
        for (int j = 0; j < 6; ++j) {
            float lo, hi; unpack2(acc2[r][j], lo, hi);
            tp[j] = fmaxf(lo + hi + b1[tx * 6 + j], 0.f);
        }
    }
    __syncthreads();

    // ---- interleaved w2 load ----
    #pragma unroll
    for (int i = 0; i < 18; ++i) {
        int idx = tid + 256 * i;
        int p = idx / 96, j = idx % 96;
        sW[idx] = pack2(w2[(2 * p) * D + j], w2[(2 * p + 1) * D + j]);
    }
    __syncthreads();

    // ---- phase 2: out = tmp @ w2 + b2 ----
    #pragma unroll
    for (int r = 0; r < 4; ++r)
        #pragma unroll
        for (int j = 0; j < 6; ++j) acc2[r][j] = pack2(0.f, 0.f);

    #pragma unroll 4
    for (int p = 0; p < D / 2; ++p) {
        ull a2[4];
        #pragma unroll
        for (int r = 0; r < 4; ++r)
            a2[r] = *reinterpret_cast<const ull*>(sTmp + (ty * 4 + r) * IN_LD + 2 * p);
        const ull* bp = sW + p * 96 + tx * 6;
        ull b0 = bp[0], b1v = bp[1], b2v = bp[2], b3 = bp[3], b4 = bp[4], b5 = bp[5];
        #pragma unroll
        for (int r = 0; r < 4; ++r) {
            fma2(acc2[r][0], a2[r], b0);
            fma2(acc2[r][1], a2[r], b1v);
            fma2(acc2[r][2], a2[r], b2v);
            fma2(acc2[r][3], a2[r], b3);
            fma2(acc2[r][4], a2[r], b4);
            fma2(acc2[r][5], a2[r], b5);
        }
    }

    #pragma unroll
    for (int r = 0; r < 4; ++r) {
        int row = rowBase + ty * 4 + r;
        if (row >= N_NODES) continue;
        float* op = dst + (size_t)row * OUT_COLS + tx * 6;
        #pragma unroll
        for (int jj = 0; jj < 3; ++jj) {
            float lo0, hi0, lo1, hi1;
            unpack2(acc2[r][jj * 2 + 0], lo0, hi0);
            unpack2(acc2[r][jj * 2 + 1], lo1, hi1);
            float2 o;
            o.x = lo0 + hi0 + b2[tx * 6 + jj * 2 + 0];
            o.y = lo1 + hi1 + b2[tx * 6 + jj * 2 + 1];
            *reinterpret_cast<float2*>(op + jj * 2) = o;
        }
    }
}

// ---------------------------------------------------------------------------
extern "C" void kernel_launch(void* const* d_in, const int* in_sizes, int n_in,
                              void* d_out, int out_size) {
    const float* x  = (const float*)d_in[0];
    const int*   ei = (const int*)d_in[1];
    const float* W[12];
    for (int i = 0; i < 12; ++i) W[i] = (const float*)d_in[2 + i];
    float* out = (float*)d_out;

    const int SMEM_BYTES = 36864 + 2 * M_TILE * IN_LD * (int)sizeof(float); // 88064
    cudaFuncSetAttribute(fused_layer_kernel,
                         cudaFuncAttributeMaxDynamicSharedMemorySize, SMEM_BYTES);

    // CSR build
    void* cnt_ptr = nullptr;
    cudaGetSymbolAddress(&cnt_ptr, g_cnt);
    cudaMemsetAsync(cnt_ptr, 0, N_NODES * sizeof(int));
    count_kernel<<<(N_EDGES + 255) / 256, 256>>>(ei);
    scan_a_kernel<<<SCAN_NB, SCAN_BS>>>();
    scan_b_kernel<<<1, 128>>>();
    scan_c_kernel<<<(N_NODES + 255) / 256, 256>>>();
    fill_kernel<<<(N_EDGES + 255) / 256, 256>>>(ei);

    const int GRID = (N_NODES + M_TILE - 1) / M_TILE;   // 782
    for (int l = 0; l < 3; ++l) {
        const float* cur = (l == 0) ? x : out + (size_t)l * D;
        int cs           = (l == 0) ? D : OUT_COLS;
        float* self0     = (l == 0) ? out : nullptr;    // S0 = x
        float* dst       = out + (size_t)(l + 1) * D;   // S_{l+1}
        fused_layer_kernel<<<GRID, 256, SMEM_BYTES>>>(
            cur, cs, W[4 * l + 0], W[4 * l + 1], W[4 * l + 2], W[4 * l + 3],
            self0, dst);
    }
}

// round 17
// speedup vs baseline: 1.4120x; 1.4120x over previous
#include <cuda_runtime.h>
#include <cuda_bf16.h>
#include <cstdint>

#define N_NODES   50000
#define N_EDGES   800000
#define D         96
#define OUT_COLS  384
#define MT        64              // rows per MMA CTA
#define SCAN_BS   512
#define SCAN_NB   ((N_NODES + SCAN_BS - 1) / SCAN_BS)

// CSR + aggregation + bf16-weight scratch
__device__ int g_cnt[N_NODES];
__device__ int g_rowptr[N_NODES + 1];
__device__ int g_csr[N_EDGES];
__device__ int g_blksum[SCAN_NB];
__device__ int g_blkoff[SCAN_NB];
__device__ __align__(16) float g_aggr[N_NODES * D];
// 6 matrices x {hi,lo} x [n*96+k]  (B-operand layout, n rows, k contiguous)
__device__ __align__(16) __nv_bfloat16 g_wbf[6 * 2 * D * D];

// ---- helpers ----------------------------------------------------------------
__device__ __forceinline__ uint32_t bpak(float e0, float e1) {  // low bits = e0
    uint32_t r;
    asm("cvt.rn.bf16x2.f32 %0, %1, %2;" : "=r"(r) : "f"(e1), "f"(e0));
    return r;
}
__device__ __forceinline__ float rlo(float v) {
    __nv_bfloat16 h = __float2bfloat16(v);
    return v - __bfloat162float(h);
}
__device__ __forceinline__ void mma_bf16(float c[4], uint32_t a0, uint32_t a1,
                                         uint32_t a2, uint32_t a3,
                                         uint32_t b0, uint32_t b1) {
    asm volatile(
        "mma.sync.aligned.m16n8k16.row.col.f32.bf16.bf16.f32 "
        "{%0,%1,%2,%3}, {%4,%5,%6,%7}, {%8,%9}, {%0,%1,%2,%3};"
        : "+f"(c[0]), "+f"(c[1]), "+f"(c[2]), "+f"(c[3])
        : "r"(a0), "r"(a1), "r"(a2), "r"(a3), "r"(b0), "r"(b1));
}

// --------------------------- CSR build ---------------------------------------
__global__ void count_kernel(const int* __restrict__ ei) {
    int e = blockIdx.x * blockDim.x + threadIdx.x;
    if (e < N_EDGES) atomicAdd(&g_cnt[ei[N_EDGES + e]], 1);
}
__global__ void scan_a_kernel() {
    __shared__ int sh[SCAN_BS];
    int t = threadIdx.x, i = blockIdx.x * SCAN_BS + t;
    int v = (i < N_NODES) ? g_cnt[i] : 0;
    sh[t] = v; __syncthreads();
    for (int off = 1; off < SCAN_BS; off <<= 1) {
        int u = (t >= off) ? sh[t - off] : 0;
        __syncthreads(); sh[t] += u; __syncthreads();
    }
    if (i < N_NODES) g_rowptr[i] = sh[t] - v;
    if (t == SCAN_BS - 1) g_blksum[blockIdx.x] = sh[t];
}
__global__ void scan_b_kernel() {
    __shared__ int sh[128];
    int t = threadIdx.x;
    int v = (t < SCAN_NB) ? g_blksum[t] : 0;
    sh[t] = v; __syncthreads();
    for (int off = 1; off < 128; off <<= 1) {
        int u = (t >= off) ? sh[t - off] : 0;
        __syncthreads(); sh[t] += u; __syncthreads();
    }
    if (t < SCAN_NB) g_blkoff[t] = sh[t] - v;
}
__global__ void scan_c_kernel() {
    int i = blockIdx.x * blockDim.x + threadIdx.x;
    if (i < N_NODES) {
        int r = g_rowptr[i] + g_blkoff[i / SCAN_BS];
        g_rowptr[i] = r; g_cnt[i] = r;
    }
    if (i == 0) g_rowptr[N_NODES] = N_EDGES;
}
__global__ void fill_kernel(const int* __restrict__ ei) {
    int e = blockIdx.x * blockDim.x + threadIdx.x;
    if (e >= N_EDGES) return;
    int pos = atomicAdd(&g_cnt[ei[N_EDGES + e]], 1);
    g_csr[pos] = ei[e];
}

// w [k][n] row-major -> g_wbf[mat]: hi/lo in [n][k] layout
__global__ void wconv_kernel(const float* __restrict__ w, int mat) {
    int idx = blockIdx.x * blockDim.x + threadIdx.x;   // k*96+n
    if (idx >= D * D) return;
    int k = idx / D, n = idx % D;
    float v = w[idx];
    __nv_bfloat16 h = __float2bfloat16(v);
    __nv_bfloat16* hi = g_wbf + (size_t)mat * 2 * D * D;
    hi[n * D + k]         = h;
    hi[D * D + n * D + k] = __float2bfloat16(v - __bfloat162float(h));
}

// ---------------------------------------------------------------------------
// gather: g_aggr[n] = cur[n] + sum_neighbors cur[src]   (cur row stride cs)
// ---------------------------------------------------------------------------
__global__ void gather_kernel(const float* __restrict__ cur, int cs,
                              float* __restrict__ self0) {
    const int n = blockIdx.x * 16 + threadIdx.x / 24;
    const int c = threadIdx.x % 24;
    if (n >= N_NODES) return;
    const int cs4 = cs / 4;
    const float4* curv = reinterpret_cast<const float4*>(cur);
    float4 acc = __ldg(&curv[(size_t)n * cs4 + c]);
    if (self0)
        *reinterpret_cast<float4*>(self0 + (size_t)n * OUT_COLS + c * 4) = acc;
    int j = g_rowptr[n], end = g_rowptr[n + 1];
    for (; j + 4 <= end; j += 4) {
        int s0 = g_csr[j], s1 = g_csr[j+1], s2 = g_csr[j+2], s3 = g_csr[j+3];
        float4 v0 = __ldg(&curv[(size_t)s0 * cs4 + c]);
        float4 v1 = __ldg(&curv[(size_t)s1 * cs4 + c]);
        float4 v2 = __ldg(&curv[(size_t)s2 * cs4 + c]);
        float4 v3 = __ldg(&curv[(size_t)s3 * cs4 + c]);
        acc.x += (v0.x + v1.x) + (v2.x + v3.x);
        acc.y += (v0.y + v1.y) + (v2.y + v3.y);
        acc.z += (v0.z + v1.z) + (v2.z + v3.z);
        acc.w += (v0.w + v1.w) + (v2.w + v3.w);
    }
    for (; j < end; ++j) {
        float4 v = __ldg(&curv[(size_t)g_csr[j] * cs4 + c]);
        acc.x += v.x; acc.y += v.y; acc.z += v.z; acc.w += v.w;
    }
    *reinterpret_cast<float4*>(g_aggr + (size_t)n * D + c * 4) = acc;
}

// ---------------------------------------------------------------------------
// MMA MLP via mma.sync m16n8k16 bf16, 2-term split (hi/lo), fp32 accum.
// 128 threads = 4 warps; warp w computes rows [base+16w, base+16w+16) x 96.
// Phase-1 accumulators ARE phase-2 A fragments (identical thread mapping):
// relu+bias+split happen in registers.
// smem (uint32 view): A_hi[64][52], A_lo[64][52], W_hi[96][52], W_lo[96][52]
// ld=52 u32 (104 bf16) -> conflict-free quad pattern. Total 66560 B.
// ---------------------------------------------------------------------------
#define ALD 52
__global__ __launch_bounds__(128) void mma_mlp_kernel(
        const __nv_bfloat16* __restrict__ w1bf,   // [hi|lo] packs, [n][k]
        const __nv_bfloat16* __restrict__ w2bf,
        const float* __restrict__ b1, const float* __restrict__ b2,
        float* __restrict__ dst) {
    extern __shared__ uint32_t sm[];
    uint32_t* sAh = sm;                    // 64*52
    uint32_t* sAl = sAh + MT * ALD;
    uint32_t* sWh = sAl + MT * ALD;        // 96*52
    uint32_t* sWl = sWh + D * ALD;

    const int tid  = threadIdx.x;
    const int lane = tid & 31, warp = tid >> 5;
    const int g = lane >> 2, tg = lane & 3;
    const int rowBase = blockIdx.x * MT;

    // ---- load A tile (fp32 -> bf16 hi/lo) ----
    const float2* av = reinterpret_cast<const float2*>(g_aggr);
    #pragma unroll
    for (int i = tid; i < MT * (D / 2); i += 128) {
        int r = i / (D / 2), kp = i % (D / 2);
        int row = rowBase + r;
        float2 v = make_float2(0.f, 0.f);
        if (row < N_NODES) v = __ldg(&av[(size_t)row * (D / 2) + kp]);
        sAh[r * ALD + kp] = bpak(__bfloat162float(__float2bfloat16(v.x)),
                                 __bfloat162float(__float2bfloat16(v.y)));
        // recompute hi floats to form exact residuals
        float hx = __bfloat162float(__float2bfloat16(v.x));
        float hy = __bfloat162float(__float2bfloat16(v.y));
        sAh[r * ALD + kp] = bpak(v.x, v.y);            // rn-packed hi
        // NOTE: bpak rounds; derive residual against the packed value:
        uint32_t hp = sAh[r * ALD + kp];
        __nv_bfloat162 hb = *reinterpret_cast<__nv_bfloat162*>(&hp);
        hx = __bfloat162float(hb.x); hy = __bfloat162float(hb.y);
        sAl[r * ALD + kp] = bpak(v.x - hx, v.y - hy);
    }
    // ---- load W1 (pre-split bf16, just insert row padding) ----
    const uint32_t* w1h = reinterpret_cast<const uint32_t*>(w1bf);
    const uint32_t* w1l = w1h + D * (D / 2);
    #pragma unroll
    for (int i = tid; i < D * (D / 2); i += 128) {
        int n = i / (D / 2), kp = i % (D / 2);
        sWh[n * ALD + kp] = __ldg(&w1h[i]);
        sWl[n * ALD + kp] = __ldg(&w1l[i]);
    }
    __syncthreads();

    // ---- phase 1: C = A @ W1 (split: hh + hl + lh) ----
    float C[12][4];
    #pragma unroll
    for (int nt = 0; nt < 12; ++nt)
        #pragma unroll
        for (int q = 0; q < 4; ++q) C[nt][q] = 0.f;

    const int ar0 = warp * 16 + g, ar1 = ar0 + 8;
    #pragma unroll
    for (int kc = 0; kc < 6; ++kc) {
        int ac = kc * 8 + tg;
        uint32_t ah0 = sAh[ar0 * ALD + ac],     ah1 = sAh[ar1 * ALD + ac];
        uint32_t ah2 = sAh[ar0 * ALD + ac + 4], ah3 = sAh[ar1 * ALD + ac + 4];
        uint32_t al0 = sAl[ar0 * ALD + ac],     al1 = sAl[ar1 * ALD + ac];
        uint32_t al2 = sAl[ar0 * ALD + ac + 4], al3 = sAl[ar1 * ALD + ac + 4];
        #pragma unroll
        for (int nt = 0; nt < 12; ++nt) {
            int bn = nt * 8 + g;
            uint32_t bh0 = sWh[bn * ALD + kc * 8 + tg];
            uint32_t bh1 = sWh[bn * ALD + kc * 8 + tg + 4];
            uint32_t bl0 = sWl[bn * ALD + kc * 8 + tg];
            uint32_t bl1 = sWl[bn * ALD + kc * 8 + tg + 4];
            mma_bf16(C[nt], ah0, ah1, ah2, ah3, bh0, bh1);
            mma_bf16(C[nt], ah0, ah1, ah2, ah3, bl0, bl1);
            mma_bf16(C[nt], al0, al1, al2, al3, bh0, bh1);
        }
    }

    // ---- epilogue 1 (registers only): relu + b1, split -> phase-2 A frags ----
    uint32_t A2h[6][4], A2l[6][4];
    #pragma unroll
    for (int kc = 0; kc < 6; ++kc) {
        #pragma unroll
        for (int h = 0; h < 2; ++h) {
            int nt = 2 * kc + h;
            int col = nt * 8 + tg * 2;
            float bb0 = __ldg(&b1[col]), bb1 = __ldg(&b1[col + 1]);
            float v0 = fmaxf(C[nt][0] + bb0, 0.f), v1 = fmaxf(C[nt][1] + bb1, 0.f);
            float v2 = fmaxf(C[nt][2] + bb0, 0.f), v3 = fmaxf(C[nt][3] + bb1, 0.f);
            A2h[kc][2 * h]     = bpak(v0, v1);
            A2h[kc][2 * h + 1] = bpak(v2, v3);
            A2l[kc][2 * h]     = bpak(rlo(v0), rlo(v1));
            A2l[kc][2 * h + 1] = bpak(rlo(v2), rlo(v3));
        }
    }

    // ---- swap in W2 ----
    __syncthreads();
    const uint32_t* w2h = reinterpret_cast<const uint32_t*>(w2bf);
    const uint32_t* w2l = w2h + D * (D / 2);
    #pragma unroll
    for (int i = tid; i < D * (D / 2); i += 128) {
        int n = i / (D / 2), kp = i % (D / 2);
        sWh[n * ALD + kp] = __ldg(&w2h[i]);
        sWl[n * ALD + kp] = __ldg(&w2l[i]);
    }
    __syncthreads();

    // ---- phase 2: C = A2 @ W2 ----
    #pragma unroll
    for (int nt = 0; nt < 12; ++nt)
        #pragma unroll
        for (int q = 0; q < 4; ++q) C[nt][q] = 0.f;

    #pragma unroll
    for (int kc = 0; kc < 6; ++kc) {
        #pragma unroll
        for (int nt = 0; nt < 12; ++nt) {
            int bn = nt * 8 + g;
            uint32_t bh0 = sWh[bn * ALD + kc * 8 + tg];
            uint32_t bh1 = sWh[bn * ALD + kc * 8 + tg + 4];
            uint32_t bl0 = sWl[bn * ALD + kc * 8 + tg];
            uint32_t bl1 = sWl[bn * ALD + kc * 8 + tg + 4];
            mma_bf16(C[nt], A2h[kc][0], A2h[kc][1], A2h[kc][2], A2h[kc][3], bh0, bh1);
            mma_bf16(C[nt], A2h[kc][0], A2h[kc][1], A2h[kc][2], A2h[kc][3], bl0, bl1);
            mma_bf16(C[nt], A2l[kc][0], A2l[kc][1], A2l[kc][2], A2l[kc][3], bh0, bh1);
        }
    }

    // ---- store: dst[row] = C + b2 ----
    int row0 = rowBase + warp * 16 + g, row1 = row0 + 8;
    #pragma unroll
    for (int nt = 0; nt < 12; ++nt) {
        int col = nt * 8 + tg * 2;
        float bb0 = __ldg(&b2[col]), bb1 = __ldg(&b2[col + 1]);
        if (row0 < N_NODES) {
            float2 o; o.x = C[nt][0] + bb0; o.y = C[nt][1] + bb1;
            *reinterpret_cast<float2*>(dst + (size_t)row0 * OUT_COLS + col) = o;
        }
        if (row1 < N_NODES) {
            float2 o; o.x = C[nt][2] + bb0; o.y = C[nt][3] + bb1;
            *reinterpret_cast<float2*>(dst + (size_t)row1 * OUT_COLS + col) = o;
        }
    }
}

// ---------------------------------------------------------------------------
extern "C" void kernel_launch(void* const* d_in, const int* in_sizes, int n_in,
                              void* d_out, int out_size) {
    const float* x  = (const float*)d_in[0];
    const int*   ei = (const int*)d_in[1];
    const float* W[12];
    for (int i = 0; i < 12; ++i) W[i] = (const float*)d_in[2 + i];
    float* out = (float*)d_out;

    const int SMEM_BYTES = (2 * MT * ALD + 2 * D * ALD) * 4;   // 66560
    cudaFuncSetAttribute(mma_mlp_kernel,
                         cudaFuncAttributeMaxDynamicSharedMemorySize, SMEM_BYTES);

    void* cnt_ptr = nullptr;
    cudaGetSymbolAddress(&cnt_ptr, g_cnt);
    cudaMemsetAsync(cnt_ptr, 0, N_NODES * sizeof(int));
    count_kernel<<<(N_EDGES + 255) / 256, 256>>>(ei);
    scan_a_kernel<<<SCAN_NB, SCAN_BS>>>();
    scan_b_kernel<<<1, 128>>>();
    scan_c_kernel<<<(N_NODES + 255) / 256, 256>>>();
    fill_kernel<<<(N_EDGES + 255) / 256, 256>>>(ei);

    // pre-split all 6 weight matrices to bf16 hi/lo (B-operand layout)
    for (int m = 0; m < 6; ++m)
        wconv_kernel<<<(D * D + 255) / 256, 256>>>(W[(m / 2) * 4 + (m % 2) * 2], m);

    void* wbf_ptr = nullptr;
    cudaGetSymbolAddress(&wbf_ptr, g_wbf);
    const __nv_bfloat16* wbf = (const __nv_bfloat16*)wbf_ptr;

    const int GGRID = (N_NODES + 15) / 16;
    const int MGRID = (N_NODES + MT - 1) / MT;
    for (int l = 0; l < 3; ++l) {
        const float* cur = (l == 0) ? x : out + (size_t)l * D;
        int cs           = (l == 0) ? D : OUT_COLS;
        float* self0     = (l == 0) ? out : nullptr;
        gather_kernel<<<GGRID, 384>>>(cur, cs, self0);
        mma_mlp_kernel<<<MGRID, 128, SMEM_BYTES>>>(
            wbf + (size_t)(2 * l) * 2 * D * D,
            wbf + (size_t)(2 * l + 1) * 2 * D * D,
            W[4 * l + 1], W[4 * l + 3],
            out + (size_t)(l + 1) * D);
    }
}